// round 5
// baseline (speedup 1.0000x reference)
#include <cuda_runtime.h>

// SNN forward: 3 layers of (GEMM + Leaky LIF), T=100 steps, B=128, fp32 I/O.
//
// Frozen numerics contract (validated rounds 3-4, rel_err 2.2e-7):
//   L0/L1: fp32 splitK=4: 4 contiguous K-chunks of 512, sequential ascending
//          FFMA within chunk, partials folded ((p0+p1)+p2)+p3.
//   L2:    fp64-exact accumulation, fp64 fold, single round to fp32.
//   LIF:   mem = 0.5*mprev + cur; mem -= reset*th  (two roundings).
//
// Round 5: 8x4 microtile (FMA-bound, not smem-bound), double-buffered smem,
// and fold+LIF fused into the GEMM via the "last CTA folds" pattern
// (atomic arrival counter per j-tile; 4th arriver folds; no waiting).

#define T_STEPS 100
#define BATCH   128

__device__ float  g_part32[4 * BATCH * 2048];   // fp32 chunk partials (L0/L1)
__device__ double g_part64[4 * BATCH * 512];    // fp64 chunk partials (L2)
__device__ int    g_cnt[64];                    // arrival counters (zero-init,
                                                // reset by folding CTA)

// ---------------------------------------------------------------------------
// fp32 GEMM chunk + fused fold/LIF.
// BM=128 (full batch), BN=64, BK=16, 256 threads, 8x4 microtile.
// grid = (H/64, 4 chunks). K fixed at 2048 (chunk = 512 = 32 tiles of 16).
// ---------------------------------------------------------------------------
__global__ void __launch_bounds__(256) gemm_lif_f32(
    const float* __restrict__ A, long lda,
    const float* __restrict__ W, int H,
    const float* __restrict__ th_ptr,
    const float* __restrict__ mem_prev,   // nullptr at t==0
    float* __restrict__ mem_out,
    float* __restrict__ spk_out)
{
    const int K = 2048;
    __shared__ __align__(16) float As[2][16][132];
    __shared__ __align__(16) float Ws[2][16][68];
    __shared__ int s_old;

    const int tid   = threadIdx.x;
    const int j0    = blockIdx.x * 64;
    const int chunk = blockIdx.y;
    const long kbase = (long)chunk * 512;

    const int tx = tid & 15;   // col group: cols j0 + tx*4 .. +3
    const int ty = tid >> 4;   // row group: rows ty*8 .. +7

    const int aro = tid >> 2;        // 0..63 (rows aro, aro+64)
    const int akv = (tid & 3) * 4;   // k offset (float4)

    float acc[8][4];
#pragma unroll
    for (int i = 0; i < 8; i++)
#pragma unroll
        for (int j = 0; j < 4; j++) acc[i][j] = 0.f;

    const float* Ab = A + kbase;
    const float* Wb = W + kbase;

    float4 aR0, aR1, wR;
    aR0 = *(const float4*)(Ab + (long)aro        * lda + akv);
    aR1 = *(const float4*)(Ab + (long)(aro + 64) * lda + akv);
    wR  = *(const float4*)(Wb + (long)(j0 + aro) * K   + akv);

    // commit tile 0 to buffer 0
    As[0][akv + 0][aro]      = aR0.x;
    As[0][akv + 1][aro]      = aR0.y;
    As[0][akv + 2][aro]      = aR0.z;
    As[0][akv + 3][aro]      = aR0.w;
    As[0][akv + 0][aro + 64] = aR1.x;
    As[0][akv + 1][aro + 64] = aR1.y;
    As[0][akv + 2][aro + 64] = aR1.z;
    As[0][akv + 3][aro + 64] = aR1.w;
    Ws[0][akv + 0][aro] = wR.x;
    Ws[0][akv + 1][aro] = wR.y;
    Ws[0][akv + 2][aro] = wR.z;
    Ws[0][akv + 3][aro] = wR.w;
    __syncthreads();

    int p = 0;
    for (int tile = 0; tile < 32; tile++) {
        const bool more = (tile + 1 < 32);
        if (more) {
            const long ko = (long)(tile + 1) * 16;
            aR0 = *(const float4*)(Ab + (long)aro        * lda + ko + akv);
            aR1 = *(const float4*)(Ab + (long)(aro + 64) * lda + ko + akv);
            wR  = *(const float4*)(Wb + (long)(j0 + aro) * K   + ko + akv);
        }

#pragma unroll
        for (int kk = 0; kk < 16; kk++) {
            float4 a0 = *(const float4*)&As[p][kk][ty * 8];
            float4 a1 = *(const float4*)&As[p][kk][ty * 8 + 4];
            float4 b  = *(const float4*)&Ws[p][kk][tx * 4];
#define FMA4(i, av)                               \
            acc[i][0] = fmaf(av, b.x, acc[i][0]); \
            acc[i][1] = fmaf(av, b.y, acc[i][1]); \
            acc[i][2] = fmaf(av, b.z, acc[i][2]); \
            acc[i][3] = fmaf(av, b.w, acc[i][3]);
            FMA4(0, a0.x) FMA4(1, a0.y) FMA4(2, a0.z) FMA4(3, a0.w)
            FMA4(4, a1.x) FMA4(5, a1.y) FMA4(6, a1.z) FMA4(7, a1.w)
#undef FMA4
        }

        if (more) {
            const int q = p ^ 1;
            As[q][akv + 0][aro]      = aR0.x;
            As[q][akv + 1][aro]      = aR0.y;
            As[q][akv + 2][aro]      = aR0.z;
            As[q][akv + 3][aro]      = aR0.w;
            As[q][akv + 0][aro + 64] = aR1.x;
            As[q][akv + 1][aro + 64] = aR1.y;
            As[q][akv + 2][aro + 64] = aR1.z;
            As[q][akv + 3][aro + 64] = aR1.w;
            Ws[q][akv + 0][aro] = wR.x;
            Ws[q][akv + 1][aro] = wR.y;
            Ws[q][akv + 2][aro] = wR.z;
            Ws[q][akv + 3][aro] = wR.w;
        }
        __syncthreads();
        p ^= 1;
    }

    // write chunk partials
    {
        float* dst = g_part32 + (long)chunk * (BATCH * (long)H);
#pragma unroll
        for (int i = 0; i < 8; i++) {
            const int b = ty * 8 + i;
            *(float4*)(dst + (long)b * H + j0 + tx * 4) =
                make_float4(acc[i][0], acc[i][1], acc[i][2], acc[i][3]);
        }
    }

    // last-CTA-folds: 4th arriver for this j-tile does fold + LIF
    __threadfence();
    __syncthreads();
    if (tid == 0) s_old = atomicAdd(&g_cnt[blockIdx.x], 1);
    __syncthreads();

    if (s_old == 3) {
        __threadfence();   // acquire: see all chunks' partials
        const float th = *th_ptr;
        const int  hq  = H >> 2;                // float4 per row
        const long n4  = (long)BATCH * hq;      // float4 per chunk
        const float4* p4 = (const float4*)g_part32;

        // stripe: 128 rows x 64 cols = 2048 float4, 8 per thread
        for (int e = tid; e < BATCH * 16; e += 256) {
            const int b  = e >> 4;
            const int jq = e & 15;
            const long idx = (long)b * hq + (j0 >> 2) + jq;
            float4 r0 = p4[idx];
            float4 r1 = p4[idx + n4];
            float4 r2 = p4[idx + 2 * n4];
            float4 r3 = p4[idx + 3 * n4];
            float4 mp = mem_prev ? ((const float4*)mem_prev)[idx]
                                 : make_float4(0.f, 0.f, 0.f, 0.f);
            float4 mem, spk;
#define LIF1(c)                                             \
            {                                               \
                float cur   = ((r0.c + r1.c) + r2.c) + r3.c;\
                float reset = (mp.c - th > 0.f) ? 1.f : 0.f;\
                float m     = 0.5f * mp.c + cur;            \
                m -= reset * th;                            \
                mem.c = m;                                  \
                spk.c = (m - th > 0.f) ? 1.f : 0.f;         \
            }
            LIF1(x) LIF1(y) LIF1(z) LIF1(w)
#undef LIF1
            ((float4*)mem_out)[idx] = mem;
            ((float4*)spk_out)[idx] = spk;
        }
        if (tid == 0) g_cnt[blockIdx.x] = 0;   // reset for next use
    }
}

// ---------------------------------------------------------------------------
// fp64-exact GEMM chunk + fused fold/LIF (layer 2, H=512).
// BM=128, BN=16, BK=16, 256 threads, 4x2 microtile. grid = (32, 4).
// ---------------------------------------------------------------------------
__global__ void __launch_bounds__(256) gemm_lif_f64(
    const float* __restrict__ A,
    const float* __restrict__ W,
    const float* __restrict__ th_ptr,
    const float* __restrict__ mem_prev,
    float* __restrict__ mem_out,
    float* __restrict__ spk_out)
{
    const int K = 2048, H = 512;
    __shared__ __align__(16) double As[16][130];
    __shared__ __align__(16) double Ws[16][18];
    __shared__ int s_old;

    const int tid   = threadIdx.x;
    const int j0    = blockIdx.x * 16;
    const int chunk = blockIdx.y;
    const long kbase = (long)chunk * 512;

    const int tx = tid & 7;    // cols j0 + tx*2 .. +1
    const int ty = tid >> 3;   // rows ty*4 .. +3

    const int aro = tid >> 2;
    const int akv = (tid & 3) * 4;
    const int wro = tid >> 4;        // 0..15
    const int wk  = tid & 15;        // 0..15

    double acc[4][2];
#pragma unroll
    for (int i = 0; i < 4; i++) { acc[i][0] = 0.0; acc[i][1] = 0.0; }

    const float* Ab = A + kbase;
    const float* Wb = W + kbase;

    float4 aReg[2];
    float  wReg;

    aReg[0] = *(const float4*)(Ab + (long)aro        * K + akv);
    aReg[1] = *(const float4*)(Ab + (long)(aro + 64) * K + akv);
    wReg    = Wb[(long)(j0 + wro) * K + wk];

    for (int tile = 0; tile < 32; tile++) {
        As[akv + 0][aro]      = (double)aReg[0].x;
        As[akv + 1][aro]      = (double)aReg[0].y;
        As[akv + 2][aro]      = (double)aReg[0].z;
        As[akv + 3][aro]      = (double)aReg[0].w;
        As[akv + 0][aro + 64] = (double)aReg[1].x;
        As[akv + 1][aro + 64] = (double)aReg[1].y;
        As[akv + 2][aro + 64] = (double)aReg[1].z;
        As[akv + 3][aro + 64] = (double)aReg[1].w;
        Ws[wk][wro] = (double)wReg;
        __syncthreads();

        if (tile + 1 < 32) {
            const long ko = (long)(tile + 1) * 16;
            aReg[0] = *(const float4*)(Ab + (long)aro        * K + ko + akv);
            aReg[1] = *(const float4*)(Ab + (long)(aro + 64) * K + ko + akv);
            wReg    = Wb[(long)(j0 + wro) * K + ko + wk];
        }

#pragma unroll
        for (int kk = 0; kk < 16; kk++) {
            double2 rb = *(const double2*)&Ws[kk][tx * 2];
            double2 a0 = *(const double2*)&As[kk][ty * 4];
            double2 a1 = *(const double2*)&As[kk][ty * 4 + 2];
            acc[0][0] = fma(a0.x, rb.x, acc[0][0]);
            acc[0][1] = fma(a0.x, rb.y, acc[0][1]);
            acc[1][0] = fma(a0.y, rb.x, acc[1][0]);
            acc[1][1] = fma(a0.y, rb.y, acc[1][1]);
            acc[2][0] = fma(a1.x, rb.x, acc[2][0]);
            acc[2][1] = fma(a1.x, rb.y, acc[2][1]);
            acc[3][0] = fma(a1.y, rb.x, acc[3][0]);
            acc[3][1] = fma(a1.y, rb.y, acc[3][1]);
        }
        __syncthreads();
    }

    {
        double* dst = g_part64 + (long)chunk * (BATCH * (long)H);
#pragma unroll
        for (int i = 0; i < 4; i++) {
            const int b = ty * 4 + i;
            *(double2*)(dst + (long)b * H + j0 + tx * 2) =
                make_double2(acc[i][0], acc[i][1]);
        }
    }

    __threadfence();
    __syncthreads();
    if (tid == 0) s_old = atomicAdd(&g_cnt[32 + blockIdx.x], 1);
    __syncthreads();

    if (s_old == 3) {
        __threadfence();
        const float th = *th_ptr;
        const long n = (long)BATCH * H;

        // stripe: 128 rows x 16 cols = 2048 scalars, 8 per thread
        for (int e = tid; e < BATCH * 16; e += 256) {
            const int b = e >> 4;
            const int j = e & 15;
            const long idx = (long)b * H + j0 + j;
            double r = ((g_part64[idx] + g_part64[idx + n])
                        + g_part64[idx + 2 * n]) + g_part64[idx + 3 * n];
            float cur   = (float)r;
            float mp    = mem_prev ? mem_prev[idx] : 0.f;
            float reset = (mp - th > 0.f) ? 1.f : 0.f;
            float mem   = 0.5f * mp + cur;
            mem -= reset * th;
            mem_out[idx] = mem;
            spk_out[idx] = (mem - th > 0.f) ? 1.f : 0.f;
        }
        if (tid == 0) g_cnt[32 + blockIdx.x] = 0;
    }
}

extern "C" void kernel_launch(void* const* d_in, const int* in_sizes, int n_in,
                              void* d_out, int out_size)
{
    const float* x   = (const float*)d_in[0];  // [B=128, T=100, 2048]
    const float* W0  = (const float*)d_in[1];
    const float* W1  = (const float*)d_in[2];
    const float* W2  = (const float*)d_in[3];
    const float* th0 = (const float*)d_in[4];
    const float* th1 = (const float*)d_in[5];
    const float* th2 = (const float*)d_in[6];

    float* out = (float*)d_out;

    const long S0 = (long)T_STEPS * BATCH * 2048;
    const long S2 = (long)T_STEPS * BATCH * 512;

    float* spk0 = out;
    float* spk1 = out + S0;
    float* spk2 = out + 2 * S0;
    float* mem0 = out + 2 * S0 + S2;
    float* mem1 = mem0 + S0;
    float* mem2 = mem1 + S0;

    const long ldx = (long)T_STEPS * 2048;

    for (int t = 0; t < T_STEPS; t++) {
        const long o0 = (long)t * BATCH * 2048;
        const long o2 = (long)t * BATCH * 512;

        gemm_lif_f32<<<dim3(32, 4), 256>>>(
            x + (long)t * 2048, ldx, W0, 2048, th0,
            t ? (mem0 + o0 - (long)BATCH * 2048) : nullptr,
            mem0 + o0, spk0 + o0);

        gemm_lif_f32<<<dim3(32, 4), 256>>>(
            spk0 + o0, 2048L, W1, 2048, th1,
            t ? (mem1 + o0 - (long)BATCH * 2048) : nullptr,
            mem1 + o0, spk1 + o0);

        gemm_lif_f64<<<dim3(32, 4), 256>>>(
            spk1 + o0, W2, th2,
            t ? (mem2 + o2 - (long)BATCH * 512) : nullptr,
            mem2 + o2, spk2 + o2);
    }
}